// round 7
// baseline (speedup 1.0000x reference)
#include <cuda_runtime.h>
#include <cuda_bf16.h>
#include <cstddef>

// Problem constants
#define BSZ 4
#define NSEQ 2048
#define DMODEL 512
#define NHEAD 8
#define DKH 64
#define MROWS (BSZ * NSEQ)          // 8192
#define SCALE 0.125f                 // 1/sqrt(64)

typedef unsigned long long ull;

// ---- packed f32x2 helpers (sm_100+: FFMA2 on the fma pipe) -----------------
__device__ __forceinline__ ull pack2(float lo, float hi) {
    ull r; asm("mov.b64 %0, {%1, %2};" : "=l"(r) : "f"(lo), "f"(hi)); return r;
}
__device__ __forceinline__ void unpack2(ull v, float& lo, float& hi) {
    asm("mov.b64 {%0, %1}, %2;" : "=f"(lo), "=f"(hi) : "l"(v));
}
__device__ __forceinline__ ull fma2(ull a, ull b, ull c) {
    ull d; asm("fma.rn.f32x2 %0, %1, %2, %3;" : "=l"(d) : "l"(a), "l"(b), "l"(c)); return d;
}
__device__ __forceinline__ ull mul2(ull a, ull b) {
    ull d; asm("mul.rn.f32x2 %0, %1, %2;" : "=l"(d) : "l"(a), "l"(b)); return d;
}

// Scratch (device globals -- no runtime allocation allowed)
__device__ float g_Qh[BSZ * NHEAD * NSEQ * DKH];   // [b][h][n][dk]
__device__ float g_Kh[BSZ * NHEAD * NSEQ * DKH];
__device__ float g_Vh[BSZ * NHEAD * NSEQ * DKH];
__device__ float g_Y [BSZ * NSEQ * DMODEL];        // [b][n][d]

// ---------------------------------------------------------------------------
// Core SGEMM body: out[m,o] = rmask[m] * sum_k X[m,k] * W[o,k]
// (X: 8192 x 512, W: 512 x 512, row-major, W used transposed = nn.Linear)
// 128x128 tile, 256 threads, 8x8 microtile, K-chunk 8, packed f32x2 FMA,
// double-buffered smem (1 barrier / chunk, LDG prefetch overlapped).
// headsplit=1 -> scatter to [b][h][n][dk]; else flat [m][o].
// ---------------------------------------------------------------------------
__device__ __forceinline__ void gemm_body(
    const float* __restrict__ X, const float* __restrict__ W,
    const float* __restrict__ rmask, float* __restrict__ out,
    int headsplit, int bx, int by,
    float As[2][8][132], float Bs[2][8][132])
{
    const int tid = threadIdx.x;
    const int m0 = by * 128, n0 = bx * 128;

    // loader mapping: 128 rows x 8 cols = 1 float4 per row per matrix
    const int lr = tid >> 1;            // 0..127
    const int lc = (tid & 1) * 4;       // 0 or 4

    // compute mapping: 16x16 thread grid, 8x8 microtile
    const int tx = (tid & 15) * 8;      // col offset in tile (8-aligned)
    const int ty = (tid >> 4) * 8;      // row offset in tile

    const float* Xrow = &X[(size_t)(m0 + lr) * 512 + lc];
    const float* Wrow = &W[(size_t)(n0 + lr) * 512 + lc];

    ull acc2[8][4];                     // 8 rows x 4 col-pairs
#pragma unroll
    for (int i = 0; i < 8; i++)
#pragma unroll
        for (int j = 0; j < 4; j++) acc2[i][j] = 0ULL;

    // prologue: stage 0
    {
        float4 a = *(const float4*)&Xrow[0];
        float4 w = *(const float4*)&Wrow[0];
        As[0][lc + 0][lr] = a.x; As[0][lc + 1][lr] = a.y;
        As[0][lc + 2][lr] = a.z; As[0][lc + 3][lr] = a.w;
        Bs[0][lc + 0][lr] = w.x; Bs[0][lc + 1][lr] = w.y;
        Bs[0][lc + 2][lr] = w.z; Bs[0][lc + 3][lr] = w.w;
    }
    __syncthreads();

    int st = 0;
    for (int k0 = 0; k0 < 512; k0 += 8, st ^= 1) {
        // prefetch next chunk into registers (overlaps with compute below)
        float4 an, wn;
        const bool more = (k0 + 8) < 512;
        if (more) {
            an = *(const float4*)&Xrow[k0 + 8];
            wn = *(const float4*)&Wrow[k0 + 8];
        }
#pragma unroll
        for (int kk = 0; kk < 8; kk++) {
            float4 a0 = *(const float4*)&As[st][kk][ty];
            float4 a1 = *(const float4*)&As[st][kk][ty + 4];
            const ulonglong2* bp = (const ulonglong2*)&Bs[st][kk][tx];
            ulonglong2 bA = bp[0];   // col pairs (0,1),(2,3)
            ulonglong2 bB = bp[1];   // col pairs (4,5),(6,7)
            const float av[8] = {a0.x, a0.y, a0.z, a0.w, a1.x, a1.y, a1.z, a1.w};
#pragma unroll
            for (int i = 0; i < 8; i++) {
                ull ad = pack2(av[i], av[i]);       // broadcast dup (alu pipe)
                acc2[i][0] = fma2(ad, bA.x, acc2[i][0]);
                acc2[i][1] = fma2(ad, bA.y, acc2[i][1]);
                acc2[i][2] = fma2(ad, bB.x, acc2[i][2]);
                acc2[i][3] = fma2(ad, bB.y, acc2[i][3]);
            }
        }
        if (more) {
            const int sn = st ^ 1;
            As[sn][lc + 0][lr] = an.x; As[sn][lc + 1][lr] = an.y;
            As[sn][lc + 2][lr] = an.z; As[sn][lc + 3][lr] = an.w;
            Bs[sn][lc + 0][lr] = wn.x; Bs[sn][lc + 1][lr] = wn.y;
            Bs[sn][lc + 2][lr] = wn.z; Bs[sn][lc + 3][lr] = wn.w;
            __syncthreads();   // single barrier per chunk
        }
    }

    // Epilogue. tx is 8-aligned so 8 output cols never cross a 64-col head boundary.
#pragma unroll
    for (int i = 0; i < 8; i++) {
        const int m = m0 + ty + i;
        const float rm = rmask[m];
        const ull rmd = pack2(rm, rm);
        const int b = m >> 11, n = m & 2047;
        const int o = n0 + tx;
        float* dst;
        if (headsplit) {
            const int h = o >> 6, dk = o & 63;
            dst = &out[((((size_t)b * NHEAD + h) * NSEQ) + n) * DKH + dk];
        } else {
            dst = &out[(size_t)m * 512 + o];
        }
        ull* d2 = (ull*)dst;            // 8-aligned float offset -> 32B aligned
#pragma unroll
        for (int j = 0; j < 4; j++) d2[j] = mul2(acc2[i][j], rmd);
    }
}

// Fused Q/K/V projection: blockIdx.z in {0,1,2} selects operand set.
// One launch of 768 CTAs instead of 3 x 256 -> better wave packing.
__global__ void __launch_bounds__(256, 2)
qkv_proj_kernel(const float* __restrict__ Q, const float* __restrict__ K,
                const float* __restrict__ V,
                const float* __restrict__ WQ, const float* __restrict__ WK,
                const float* __restrict__ WV,
                const float* __restrict__ qm, const float* __restrict__ km,
                float* __restrict__ oQ, float* __restrict__ oK,
                float* __restrict__ oV)
{
    __shared__ __align__(16) float As[2][8][132];
    __shared__ __align__(16) float Bs[2][8][132];
    const int z = blockIdx.z;
    const float* X  = (z == 0) ? Q  : (z == 1) ? K  : V;
    const float* W  = (z == 0) ? WQ : (z == 1) ? WK : WV;
    const float* rm = (z == 0) ? qm : km;
    float* out      = (z == 0) ? oQ : (z == 1) ? oK : oV;
    gemm_body(X, W, rm, out, 1, blockIdx.x, blockIdx.y, As, Bs);
}

// Output projection (flat layout)
__global__ void __launch_bounds__(256, 2)
out_proj_kernel(const float* __restrict__ X, const float* __restrict__ W,
                const float* __restrict__ rmask, float* __restrict__ out)
{
    __shared__ __align__(16) float As[2][8][132];
    __shared__ __align__(16) float Bs[2][8][132];
    gemm_body(X, W, rmask, out, 0, blockIdx.x, blockIdx.y, As, Bs);
}

// ---------------------------------------------------------------------------
// Fused masked attention: per (b,h), flash-style online softmax.
// Block = 128 threads = 128 query rows. K/V double-buffered in smem, tiles of
// 32 keys, packed f32x2 FMA in QK and PV. 1 barrier per tile.
// Mask row: SINGLE register buffer (32 regs). Consumed by the score pass,
// refilled for tile kt+1 right before the PV pass -> PV FMA stretch + barrier
// hide the mask DRAM latency without double-buffer register cost.
// Writes g_Y[b][n][h*64+dk] = km[b,q] * softmax(mask(QK^T/8)) V
// ---------------------------------------------------------------------------
__global__ void __launch_bounds__(128, 2)
attn_kernel(const float* __restrict__ att_mas, const float* __restrict__ k_mas)
{
    __shared__ __align__(16) ull Ks2[2][32 * 32];   // [stage][key*32 + pair]
    __shared__ __align__(16) ull Vs2[2][32 * 32];

    const int tid = threadIdx.x;
    const int h = blockIdx.y, b = blockIdx.z;
    const int qi = blockIdx.x * 128 + tid;
    const int bh = b * NHEAD + h;

    // Load query row into packed registers: q2[p] = (q[2p], q[2p+1])
    ull q2[32];
    {
        const ulonglong2* qr = (const ulonglong2*)&g_Qh[(((size_t)bh * NSEQ) + qi) * DKH];
#pragma unroll
        for (int i = 0; i < 16; i++) {
            ulonglong2 v = qr[i];
            q2[2 * i] = v.x; q2[2 * i + 1] = v.y;
        }
    }

    ull acc2[32];
#pragma unroll
    for (int d = 0; d < 32; d++) acc2[d] = 0ULL;
    float mrun = -1e30f, l = 0.f;

    const float4* mrow = (const float4*)&att_mas[((size_t)b * NSEQ + qi) * NSEQ];
    // K/V rows for this (b,h): tiles of 32 keys = 512 contiguous ulonglong2
    const ulonglong2* Kbase = (const ulonglong2*)&g_Kh[((size_t)bh * NSEQ) * DKH];
    const ulonglong2* Vbase = (const ulonglong2*)&g_Vh[((size_t)bh * NSEQ) * DKH];

    // prologue: tile 0 -> stage 0, mask chunk 0 -> registers
    float4 mreg[8];
    {
        ulonglong2* Kdst = (ulonglong2*)Ks2[0];
        ulonglong2* Vdst = (ulonglong2*)Vs2[0];
#pragma unroll
        for (int i = 0; i < 4; i++) {
            Kdst[tid + i * 128] = Kbase[tid + i * 128];
            Vdst[tid + i * 128] = Vbase[tid + i * 128];
        }
#pragma unroll
        for (int i = 0; i < 8; i++) mreg[i] = mrow[i];
    }
    __syncthreads();

    int st = 0;
    for (int kt = 0; kt < NSEQ / 32; kt++, st ^= 1) {
        const bool more = (kt + 1) < (NSEQ / 32);
        // prefetch next K/V tile into registers (front-batched LDG)
        ulonglong2 kb[4], vb[4];
        if (more) {
            const ulonglong2* Kn = Kbase + (size_t)(kt + 1) * 512;
            const ulonglong2* Vn = Vbase + (size_t)(kt + 1) * 512;
#pragma unroll
            for (int i = 0; i < 4; i++) {
                kb[i] = Kn[tid + i * 128];
                vb[i] = Vn[tid + i * 128];
            }
        }

        // ---- scores for 32 keys (packed dot products); consumes mreg ----
        float s[32];
        float tmax = -1e30f;
#pragma unroll 2
        for (int jg = 0; jg < 8; jg++) {
            const float4 mv = mreg[jg];
            float amv[4] = {mv.x, mv.y, mv.z, mv.w};
#pragma unroll
            for (int jj = 0; jj < 4; jj++) {
                const int j = jg * 4 + jj;
                const ulonglong2* kr = (const ulonglong2*)&Ks2[st][j * 32];
                ull dA = 0ULL, dB = 0ULL;
#pragma unroll
                for (int t = 0; t < 16; t++) {
                    ulonglong2 kv = kr[t];          // LDS.128 broadcast
                    dA = fma2(q2[2 * t + 0], kv.x, dA);
                    dB = fma2(q2[2 * t + 1], kv.y, dB);
                }
                float e0, e1, e2, e3;
                unpack2(dA, e0, e1);
                unpack2(dB, e2, e3);
                const float sc = ((e0 + e1) + (e2 + e3)) * SCALE;
                s[j] = (amv[jj] != 0.f) ? sc : -1e30f;
                tmax = fmaxf(tmax, s[j]);
            }
        }

        // refill mask buffer for next tile NOW: the PV pass below (~2000 cyc)
        // plus the tile barrier hide the full DRAM latency.
        if (more) {
#pragma unroll
            for (int i = 0; i < 8; i++) mreg[i] = mrow[(kt + 1) * 8 + i];
        }

        // ---- online softmax update ----
        const float mnew = fmaxf(mrun, tmax);
        const float alpha = __expf(mrun - mnew);   // ==1 while both sentinels (acc=0)
        l *= alpha;
        const ull ad = pack2(alpha, alpha);
#pragma unroll
        for (int d = 0; d < 32; d++) acc2[d] = mul2(acc2[d], ad);

#pragma unroll 4
        for (int j = 0; j < 32; j++) {
            const float p = (s[j] > -1e29f) ? __expf(s[j] - mnew) : 0.f;
            l += p;
            const ull pd = pack2(p, p);
            const ulonglong2* vr = (const ulonglong2*)&Vs2[st][j * 32];
#pragma unroll
            for (int t = 0; t < 16; t++) {
                ulonglong2 vv = vr[t];
                acc2[2 * t + 0] = fma2(pd, vv.x, acc2[2 * t + 0]);
                acc2[2 * t + 1] = fma2(pd, vv.y, acc2[2 * t + 1]);
            }
        }
        mrun = mnew;

        if (more) {
            ulonglong2* Kdst = (ulonglong2*)Ks2[st ^ 1];
            ulonglong2* Vdst = (ulonglong2*)Vs2[st ^ 1];
#pragma unroll
            for (int i = 0; i < 4; i++) {
                Kdst[tid + i * 128] = kb[i];
                Vdst[tid + i * 128] = vb[i];
            }
            __syncthreads();   // single barrier per tile
        }
    }

    const float inv = (l > 0.f) ? (1.f / l) : 0.f;  // self-edge guarantees l>0
    const float km = k_mas[b * NSEQ + qi];
    const ull scd = pack2(inv * km, inv * km);
    ull* yout = (ull*)&g_Y[(((size_t)b * NSEQ + qi) * DMODEL) + h * DKH];
#pragma unroll
    for (int d = 0; d < 32; d++) yout[d] = mul2(acc2[d], scd);
}

// ---------------------------------------------------------------------------
// Launch: fused QKV projection -> attention -> output projection
// Inputs (metadata order): Q K V q_mas k_mas att_mas WQ WK WV WO
// ---------------------------------------------------------------------------
extern "C" void kernel_launch(void* const* d_in, const int* in_sizes, int n_in,
                              void* d_out, int out_size)
{
    const float* Q   = (const float*)d_in[0];
    const float* K   = (const float*)d_in[1];
    const float* V   = (const float*)d_in[2];
    const float* qm  = (const float*)d_in[3];
    const float* km  = (const float*)d_in[4];
    const float* am  = (const float*)d_in[5];
    const float* WQ  = (const float*)d_in[6];
    const float* WK  = (const float*)d_in[7];
    const float* WV  = (const float*)d_in[8];
    const float* WO  = (const float*)d_in[9];
    float* out = (float*)d_out;

    float *pQh, *pKh, *pVh, *pY;
    cudaGetSymbolAddress((void**)&pQh, g_Qh);
    cudaGetSymbolAddress((void**)&pKh, g_Kh);
    cudaGetSymbolAddress((void**)&pVh, g_Vh);
    cudaGetSymbolAddress((void**)&pY,  g_Y);

    dim3 qkvgrid(512 / 128, MROWS / 128, 3);   // (4, 64, 3) = 768 CTAs
    qkv_proj_kernel<<<qkvgrid, 256>>>(Q, K, V, WQ, WK, WV, qm, km, pQh, pKh, pVh);

    dim3 agrid(NSEQ / 128, NHEAD, BSZ); // (16, 8, 4)
    attn_kernel<<<agrid, 128>>>(am, km);

    dim3 ogrid(512 / 128, MROWS / 128); // (4, 64)
    out_proj_kernel<<<ogrid, 256>>>(pY, WO, km, out);
}

// round 13
// speedup vs baseline: 1.8713x; 1.8713x over previous
#include <cuda_runtime.h>
#include <cuda_bf16.h>
#include <cstdint>
#include <cstddef>

// Problem constants
#define BSZ 4
#define NSEQ 2048
#define DMODEL 512
#define NHEAD 8
#define DKH 64
#define MROWS (BSZ * NSEQ)          // 8192
#define SCALE 0.125f                 // 1/sqrt(64)

typedef unsigned long long ull;

// ---- packed f32x2 helpers (GEMM path) --------------------------------------
__device__ __forceinline__ ull pack2(float lo, float hi) {
    ull r; asm("mov.b64 %0, {%1, %2};" : "=l"(r) : "f"(lo), "f"(hi)); return r;
}
__device__ __forceinline__ ull fma2(ull a, ull b, ull c) {
    ull d; asm("fma.rn.f32x2 %0, %1, %2, %3;" : "=l"(d) : "l"(a), "l"(b), "l"(c)); return d;
}
__device__ __forceinline__ ull mul2(ull a, ull b) {
    ull d; asm("mul.rn.f32x2 %0, %1, %2;" : "=l"(d) : "l"(a), "l"(b)); return d;
}

// ---- tf32 mma helpers (attention path) -------------------------------------
__device__ __forceinline__ uint32_t f2tf32(float x) {
    uint32_t r; asm("cvt.rna.tf32.f32 %0, %1;" : "=r"(r) : "f"(x)); return r;
}
__device__ __forceinline__ void mma_tf32(
    float& d0, float& d1, float& d2, float& d3,
    uint32_t a0, uint32_t a1, uint32_t a2, uint32_t a3,
    uint32_t b0, uint32_t b1)
{
    asm volatile(
        "mma.sync.aligned.m16n8k8.row.col.f32.tf32.tf32.f32 "
        "{%0,%1,%2,%3}, {%4,%5,%6,%7}, {%8,%9}, {%0,%1,%2,%3};"
        : "+f"(d0), "+f"(d1), "+f"(d2), "+f"(d3)
        : "r"(a0), "r"(a1), "r"(a2), "r"(a3), "r"(b0), "r"(b1));
}

// Scratch (device globals -- no runtime allocation allowed)
__device__ float g_Qh[BSZ * NHEAD * NSEQ * DKH];   // [b][h][n][dk]
__device__ float g_Kh[BSZ * NHEAD * NSEQ * DKH];
__device__ float g_Vh[BSZ * NHEAD * NSEQ * DKH];
__device__ float g_Y [BSZ * NSEQ * DMODEL];        // [b][n][d]

// ---------------------------------------------------------------------------
// SGEMM body (f32x2) -- passing baseline, epilogue rmask loads front-batched.
// out[m,o] = rmask[m] * sum_k X[m,k] * W[o,k]
// ---------------------------------------------------------------------------
__device__ __forceinline__ void gemm_body(
    const float* __restrict__ X, const float* __restrict__ W,
    const float* __restrict__ rmask, float* __restrict__ out,
    int headsplit, int bx, int by,
    float As[2][8][132], float Bs[2][8][132])
{
    const int tid = threadIdx.x;
    const int m0 = by * 128, n0 = bx * 128;
    const int lr = tid >> 1;
    const int lc = (tid & 1) * 4;
    const int tx = (tid & 15) * 8;
    const int ty = (tid >> 4) * 8;

    const float* Xrow = &X[(size_t)(m0 + lr) * 512 + lc];
    const float* Wrow = &W[(size_t)(n0 + lr) * 512 + lc];

    ull acc2[8][4];
#pragma unroll
    for (int i = 0; i < 8; i++)
#pragma unroll
        for (int j = 0; j < 4; j++) acc2[i][j] = 0ULL;

    {
        float4 a = *(const float4*)&Xrow[0];
        float4 w = *(const float4*)&Wrow[0];
        As[0][lc + 0][lr] = a.x; As[0][lc + 1][lr] = a.y;
        As[0][lc + 2][lr] = a.z; As[0][lc + 3][lr] = a.w;
        Bs[0][lc + 0][lr] = w.x; Bs[0][lc + 1][lr] = w.y;
        Bs[0][lc + 2][lr] = w.z; Bs[0][lc + 3][lr] = w.w;
    }
    __syncthreads();

    int st = 0;
    for (int k0 = 0; k0 < 512; k0 += 8, st ^= 1) {
        float4 an, wn;
        const bool more = (k0 + 8) < 512;
        if (more) {
            an = *(const float4*)&Xrow[k0 + 8];
            wn = *(const float4*)&Wrow[k0 + 8];
        }
#pragma unroll
        for (int kk = 0; kk < 8; kk++) {
            float4 a0 = *(const float4*)&As[st][kk][ty];
            float4 a1 = *(const float4*)&As[st][kk][ty + 4];
            const ulonglong2* bp = (const ulonglong2*)&Bs[st][kk][tx];
            ulonglong2 bA = bp[0];
            ulonglong2 bB = bp[1];
            const float av[8] = {a0.x, a0.y, a0.z, a0.w, a1.x, a1.y, a1.z, a1.w};
#pragma unroll
            for (int i = 0; i < 8; i++) {
                ull ad = pack2(av[i], av[i]);
                acc2[i][0] = fma2(ad, bA.x, acc2[i][0]);
                acc2[i][1] = fma2(ad, bA.y, acc2[i][1]);
                acc2[i][2] = fma2(ad, bB.x, acc2[i][2]);
                acc2[i][3] = fma2(ad, bB.y, acc2[i][3]);
            }
        }
        if (more) {
            const int sn = st ^ 1;
            As[sn][lc + 0][lr] = an.x; As[sn][lc + 1][lr] = an.y;
            As[sn][lc + 2][lr] = an.z; As[sn][lc + 3][lr] = an.w;
            Bs[sn][lc + 0][lr] = wn.x; Bs[sn][lc + 1][lr] = wn.y;
            Bs[sn][lc + 2][lr] = wn.z; Bs[sn][lc + 3][lr] = wn.w;
            __syncthreads();
        }
    }

    // Epilogue: batch the 8 rmask LDGs first (MLP=8, L2-resident), then scale+store.
    float rm[8];
#pragma unroll
    for (int i = 0; i < 8; i++) rm[i] = rmask[m0 + ty + i];

#pragma unroll
    for (int i = 0; i < 8; i++) {
        const int m = m0 + ty + i;
        const ull rmd = pack2(rm[i], rm[i]);
        const int b = m >> 11, n = m & 2047;
        const int o = n0 + tx;
        float* dst;
        if (headsplit) {
            const int h = o >> 6, dk = o & 63;
            dst = &out[((((size_t)b * NHEAD + h) * NSEQ) + n) * DKH + dk];
        } else {
            dst = &out[(size_t)m * 512 + o];
        }
        ull* d2 = (ull*)dst;
#pragma unroll
        for (int j = 0; j < 4; j++) d2[j] = mul2(acc2[i][j], rmd);
    }
}

__global__ void __launch_bounds__(256, 2)
qkv_proj_kernel(const float* __restrict__ Q, const float* __restrict__ K,
                const float* __restrict__ V,
                const float* __restrict__ WQ, const float* __restrict__ WK,
                const float* __restrict__ WV,
                const float* __restrict__ qm, const float* __restrict__ km,
                float* __restrict__ oQ, float* __restrict__ oK,
                float* __restrict__ oV)
{
    __shared__ __align__(16) float As[2][8][132];
    __shared__ __align__(16) float Bs[2][8][132];
    const int z = blockIdx.z;
    const float* X  = (z == 0) ? Q  : (z == 1) ? K  : V;
    const float* W  = (z == 0) ? WQ : (z == 1) ? WK : WV;
    const float* rm = (z == 0) ? qm : km;
    float* out      = (z == 0) ? oQ : (z == 1) ? oK : oV;
    gemm_body(X, W, rm, out, 1, blockIdx.x, blockIdx.y, As, Bs);
}

__global__ void __launch_bounds__(256, 2)
out_proj_kernel(const float* __restrict__ X, const float* __restrict__ W,
                const float* __restrict__ rmask, float* __restrict__ out)
{
    __shared__ __align__(16) float As[2][8][132];
    __shared__ __align__(16) float Bs[2][8][132];
    gemm_body(X, W, rmask, out, 0, blockIdx.x, blockIdx.y, As, Bs);
}

// ---------------------------------------------------------------------------
// Tensor-core attention (mma.sync m16n8k8 tf32) -- audited against PTX ISA.
// CTA = 256 threads (8 warps) = 128 query rows; key tiles of 64.
// Warp w owns query rows [w*16, w*16+16). Per tile:
//   stage mask (DRAM, issued FIRST) + K/V (L2, under mask shadow) ->
//   S = Q K^T via mma -> masked online softmax (quad shfl reductions) ->
//   P (tf32) into smem (warp-private rows, __syncwarp only) -> O += P V.
// Fragment maps (PTX m16n8k8 layouts), g=lane>>2, t=lane&3:
//   A(16x8): a0=(g,t) a1=(g+8,t) a2=(g,t+4) a3=(g+8,t+4)
//   B(8x8) : b0=(k=t,n=g) b1=(k=t+4,n=g)
//   C(16x8): c0=(g,2t) c1=(g,2t+1) c2=(g+8,2t) c3=(g+8,2t+1)
// ---------------------------------------------------------------------------
#define QT 128
#define KT 64
#define PAD 68

__device__ __forceinline__ uint4 cvt4(float4 v) {
    uint4 r;
    r.x = f2tf32(v.x); r.y = f2tf32(v.y);
    r.z = f2tf32(v.z); r.w = f2tf32(v.w);
    return r;
}

__global__ void __launch_bounds__(256, 2)
attn_mma_kernel(const float* __restrict__ att_mas, const float* __restrict__ k_mas)
{
    extern __shared__ float sm[];
    float* Qs = sm;                    // [QT][PAD] tf32 bits
    float* Ks = sm + QT * PAD;         // [KT][PAD] tf32 bits
    float* Vs = Ks + KT * PAD;         // [KT][PAD] tf32 bits
    float* Ps = Vs + KT * PAD;         // [QT][PAD] mask, then P

    const int tid  = threadIdx.x;
    const int warp = tid >> 5, lane = tid & 31;
    const int g = lane >> 2, t = lane & 3;
    const int h = blockIdx.y, b = blockIdx.z;
    const int q0 = blockIdx.x * QT;
    const int bh = b * NHEAD + h;

    const float* Qg = g_Qh + ((size_t)bh * NSEQ + q0) * DKH;
    const float* Kg = g_Kh + ((size_t)bh * NSEQ) * DKH;
    const float* Vg = g_Vh + ((size_t)bh * NSEQ) * DKH;
    const float* Mg = att_mas + ((size_t)b * NSEQ + q0) * NSEQ;

    // Stage Q tile once (tf32-converted). Covered by first in-loop barrier.
    for (int i = tid; i < QT * 16; i += 256) {
        int r = i >> 4, c4 = (i & 15) << 2;
        float4 v = *(const float4*)&Qg[r * DKH + c4];
        *(uint4*)&Qs[r * PAD + c4] = cvt4(v);     // 16B-aligned: 272r + 16c
    }

    const int qb = warp * 16;

    float od[8][4];
#pragma unroll
    for (int i = 0; i < 8; i++)
#pragma unroll
        for (int j = 0; j < 4; j++) od[i][j] = 0.f;
    float m0 = -1e30f, m1 = -1e30f, l0 = 0.f, l1 = 0.f;

    for (int kt = 0; kt < NSEQ / KT; kt++) {
        __syncthreads();   // prev PV done; Qs staged (first iter)

        // ---- cooperative tile loads: mask first (DRAM-latency loads lead) ----
        for (int i = tid; i < QT * 16; i += 256) {
            int r = i >> 4, c4 = (i & 15) << 2;
            float4 mv = *(const float4*)&Mg[(size_t)r * NSEQ + kt * KT + c4];
            *(float4*)&Ps[r * PAD + c4] = mv;
        }
        const float* Ksrc = Kg + (size_t)kt * KT * DKH;
        const float* Vsrc = Vg + (size_t)kt * KT * DKH;
        for (int i = tid; i < KT * 16; i += 256) {
            int r = i >> 4, c4 = (i & 15) << 2;
            float4 kv = *(const float4*)&Ksrc[r * DKH + c4];
            float4 vv = *(const float4*)&Vsrc[r * DKH + c4];
            *(uint4*)&Ks[r * PAD + c4] = cvt4(kv);
            *(uint4*)&Vs[r * PAD + c4] = cvt4(vv);
        }
        __syncthreads();

        // ---- S = Q K^T ----
        float sc[8][4];
#pragma unroll
        for (int i = 0; i < 8; i++) { sc[i][0] = 0.f; sc[i][1] = 0.f; sc[i][2] = 0.f; sc[i][3] = 0.f; }
#pragma unroll
        for (int kc = 0; kc < 8; kc++) {
            const uint32_t* Ab = (const uint32_t*)&Qs[(qb + g) * PAD + kc * 8 + t];
            uint32_t a0 = Ab[0];
            uint32_t a1 = Ab[8 * PAD];
            uint32_t a2 = Ab[4];
            uint32_t a3 = Ab[8 * PAD + 4];
#pragma unroll
            for (int nt = 0; nt < 8; nt++) {
                const uint32_t* Bb = (const uint32_t*)&Ks[(nt * 8 + g) * PAD + kc * 8 + t];
                mma_tf32(sc[nt][0], sc[nt][1], sc[nt][2], sc[nt][3],
                         a0, a1, a2, a3, Bb[0], Bb[4]);
            }
        }

        // ---- mask + scale + tile max ----
        float tmax0 = -1e30f, tmax1 = -1e30f;
#pragma unroll
        for (int nt = 0; nt < 8; nt++) {
            int c = nt * 8 + t * 2;
            float2 mk0 = *(float2*)&Ps[(qb + g) * PAD + c];
            float2 mk1 = *(float2*)&Ps[(qb + g + 8) * PAD + c];
            sc[nt][0] = (mk0.x != 0.f) ? sc[nt][0] * SCALE : -1e30f;
            sc[nt][1] = (mk0.y != 0.f) ? sc[nt][1] * SCALE : -1e30f;
            sc[nt][2] = (mk1.x != 0.f) ? sc[nt][2] * SCALE : -1e30f;
            sc[nt][3] = (mk1.y != 0.f) ? sc[nt][3] * SCALE : -1e30f;
            tmax0 = fmaxf(tmax0, fmaxf(sc[nt][0], sc[nt][1]));
            tmax1 = fmaxf(tmax1, fmaxf(sc[nt][2], sc[nt][3]));
        }
        tmax0 = fmaxf(tmax0, __shfl_xor_sync(0xffffffffu, tmax0, 1));
        tmax0 = fmaxf(tmax0, __shfl_xor_sync(0xffffffffu, tmax0, 2));
        tmax1 = fmaxf(tmax1, __shfl_xor_sync(0xffffffffu, tmax1, 1));
        tmax1 = fmaxf(tmax1, __shfl_xor_sync(0xffffffffu, tmax1, 2));

        const float mn0 = fmaxf(m0, tmax0), mn1 = fmaxf(m1, tmax1);
        const float al0 = __expf(m0 - mn0), al1 = __expf(m1 - mn1);
#pragma unroll
        for (int i = 0; i < 8; i++) {
            od[i][0] *= al0; od[i][1] *= al0;
            od[i][2] *= al1; od[i][3] *= al1;
        }

        // ---- P = exp(S - m), write tf32 to smem; row-sum partials ----
        float ls0 = 0.f, ls1 = 0.f;
#pragma unroll
        for (int nt = 0; nt < 8; nt++) {
            float p0 = (sc[nt][0] > -1e29f) ? __expf(sc[nt][0] - mn0) : 0.f;
            float p1 = (sc[nt][1] > -1e29f) ? __expf(sc[nt][1] - mn0) : 0.f;
            float p2 = (sc[nt][2] > -1e29f) ? __expf(sc[nt][2] - mn1) : 0.f;
            float p3 = (sc[nt][3] > -1e29f) ? __expf(sc[nt][3] - mn1) : 0.f;
            ls0 += p0 + p1; ls1 += p2 + p3;
            int c = nt * 8 + t * 2;
            uint32_t* d0 = (uint32_t*)&Ps[(qb + g) * PAD + c];
            d0[0] = f2tf32(p0); d0[1] = f2tf32(p1);
            uint32_t* d1 = (uint32_t*)&Ps[(qb + g + 8) * PAD + c];
            d1[0] = f2tf32(p2); d1[1] = f2tf32(p3);
        }
        ls0 += __shfl_xor_sync(0xffffffffu, ls0, 1);
        ls0 += __shfl_xor_sync(0xffffffffu, ls0, 2);
        ls1 += __shfl_xor_sync(0xffffffffu, ls1, 1);
        ls1 += __shfl_xor_sync(0xffffffffu, ls1, 2);
        l0 = l0 * al0 + ls0;
        l1 = l1 * al1 + ls1;
        m0 = mn0; m1 = mn1;

        __syncwarp();   // P rows are warp-private; order STS before LDS

        // ---- O += P V ----
#pragma unroll
        for (int kc = 0; kc < 8; kc++) {
            const uint32_t* Ab = (const uint32_t*)&Ps[(qb + g) * PAD + kc * 8 + t];
            uint32_t a0 = Ab[0];
            uint32_t a1 = Ab[8 * PAD];
            uint32_t a2 = Ab[4];
            uint32_t a3 = Ab[8 * PAD + 4];
#pragma unroll
            for (int nt = 0; nt < 8; nt++) {
                const uint32_t* Bb = (const uint32_t*)&Vs[(kc * 8 + t) * PAD + nt * 8 + g];
                mma_tf32(od[nt][0], od[nt][1], od[nt][2], od[nt][3],
                         a0, a1, a2, a3, Bb[0], Bb[4 * PAD]);
            }
        }
    }

    // ---- epilogue: normalize, km post-mask, write g_Y ----
    const float inv0 = 1.f / l0, inv1 = 1.f / l1;   // self-edge guarantees l>0
    const int qr0 = q0 + qb + g, qr1 = qr0 + 8;
    const float s0 = k_mas[b * NSEQ + qr0] * inv0;
    const float s1 = k_mas[b * NSEQ + qr1] * inv1;
    float* Y0 = &g_Y[((size_t)b * NSEQ + qr0) * DMODEL + h * DKH];
    float* Y1 = &g_Y[((size_t)b * NSEQ + qr1) * DMODEL + h * DKH];
#pragma unroll
    for (int nt = 0; nt < 8; nt++) {
        int c = nt * 8 + t * 2;
        float2 v0 = make_float2(od[nt][0] * s0, od[nt][1] * s0);
        float2 v1 = make_float2(od[nt][2] * s1, od[nt][3] * s1);
        *(float2*)&Y0[c] = v0;
        *(float2*)&Y1[c] = v1;
    }
}

// ---------------------------------------------------------------------------
// Launch: fused QKV projection -> mma attention -> output projection
// Inputs (metadata order): Q K V q_mas k_mas att_mas WQ WK WV WO
// ---------------------------------------------------------------------------
extern "C" void kernel_launch(void* const* d_in, const int* in_sizes, int n_in,
                              void* d_out, int out_size)
{
    const float* Q   = (const float*)d_in[0];
    const float* K   = (const float*)d_in[1];
    const float* V   = (const float*)d_in[2];
    const float* qm  = (const float*)d_in[3];
    const float* km  = (const float*)d_in[4];
    const float* am  = (const float*)d_in[5];
    const float* WQ  = (const float*)d_in[6];
    const float* WK  = (const float*)d_in[7];
    const float* WV  = (const float*)d_in[8];
    const float* WO  = (const float*)d_in[9];
    float* out = (float*)d_out;

    float *pQh, *pKh, *pVh, *pY;
    cudaGetSymbolAddress((void**)&pQh, g_Qh);
    cudaGetSymbolAddress((void**)&pKh, g_Kh);
    cudaGetSymbolAddress((void**)&pVh, g_Vh);
    cudaGetSymbolAddress((void**)&pY,  g_Y);

    dim3 qkvgrid(512 / 128, MROWS / 128, 3);   // 768 CTAs
    qkv_proj_kernel<<<qkvgrid, 256>>>(Q, K, V, WQ, WK, WV, qm, km, pQh, pKh, pVh);

    const int attn_smem = (QT * PAD + KT * PAD * 2 + QT * PAD) * (int)sizeof(float); // 104448
    cudaFuncSetAttribute(attn_mma_kernel,
                         cudaFuncAttributeMaxDynamicSharedMemorySize, attn_smem);
    dim3 agrid(NSEQ / QT, NHEAD, BSZ);         // (16, 8, 4)
    attn_mma_kernel<<<agrid, 256, attn_smem>>>(am, km);

    dim3 ogrid(512 / 128, MROWS / 128);        // (4, 64)
    out_proj_kernel<<<ogrid, 256>>>(pY, WO, km, out);
}